// round 15
// baseline (speedup 1.0000x reference)
#include <cuda_runtime.h>
#include <cuda_bf16.h>
#include <cuda_fp16.h>
#include <cstdint>
#include <cstddef>

// VectorQuantizer, two-phase, screenless:
//   Phase 1: bf16 ldmatrix+mma GEMM (champion R11 hot loop, BM=64 x BN=256,
//            4 warps, 64x64 warp tiles, 2 CTAs/SM). Per-ktile epilogue keeps a
//            per-row running min in smem and appends candidates
//            (s <= runmin + MARGIN) as packed (fp16 s | u16 k) to per-row
//            smem lists. No 256MB screen matrix at all.
//   Phase 2: 64 thr/row: prune stored candidates vs final min, exact fp32
//            rescue (bit-identical Round-2 chain), fused gather + loss.
// Output: [ z_q_st (B*512) | indices as float (B) | vq_loss (1) ]

#define DDIM 512
#define NB 16384
#define NK 8192
#define BM 64
#define BN 256

#define SA 40                      // smem row stride in halves (80B, LDSM conflict-free)
#define ABUF_H (64 * SA)
#define BBUF_H (256 * SA)
#define BUF_H  (ABUF_H + BBUF_H)   // 12800 halves per pipeline buffer

#define CAP 64
#define MARGIN 2e-3f

__device__ float    g_ee[NK];
__device__ float    g_zz[NB];
__device__ float    g_rmin[NB];
__device__ int      g_ccnt[NB];
__device__ unsigned g_cand[(size_t)NB * CAP];
__device__ double   g_part[NB];

__device__ __nv_bfloat16 g_zb[NB * DDIM];
__device__ __nv_bfloat16 g_eb[NK * DDIM];

// ---- helpers -------------------------------------------------------------
__device__ __forceinline__ unsigned smem_u32(const void* p)
{
    return (unsigned)__cvta_generic_to_shared(p);
}
__device__ __forceinline__ void cp16(__half* sdst, const void* gsrc)
{
    asm volatile("cp.async.ca.shared.global [%0], [%1], 16;\n"
                 :: "r"(smem_u32(sdst)), "l"(gsrc));
}
__device__ __forceinline__ void cp_commit() { asm volatile("cp.async.commit_group;\n"); }
__device__ __forceinline__ void cp_wait0()  { asm volatile("cp.async.wait_group 0;\n"); }

__device__ __forceinline__ void ldsm4(unsigned* r, unsigned addr)
{
    asm volatile("ldmatrix.sync.aligned.m8n8.x4.shared.b16 {%0,%1,%2,%3}, [%4];"
                 : "=r"(r[0]), "=r"(r[1]), "=r"(r[2]), "=r"(r[3]) : "r"(addr));
}
__device__ __forceinline__ void mma_bf16(float* c, const unsigned* a,
                                         unsigned b0, unsigned b1)
{
    asm volatile(
        "mma.sync.aligned.m16n8k16.row.col.f32.bf16.bf16.f32 "
        "{%0,%1,%2,%3}, {%4,%5,%6,%7}, {%8,%9}, {%0,%1,%2,%3};\n"
        : "+f"(c[0]), "+f"(c[1]), "+f"(c[2]), "+f"(c[3])
        : "r"(a[0]), "r"(a[1]), "r"(a[2]), "r"(a[3]), "r"(b0), "r"(b1));
}

// ---- prep ----------------------------------------------------------------
__global__ void to_bf16_both_kernel(const float* __restrict__ z,
                                    const float* __restrict__ emb,
                                    __nv_bfloat16* __restrict__ zb,
                                    __nv_bfloat16* __restrict__ eb,
                                    int nz4, int ne4)
{
    int i = blockIdx.x * blockDim.x + threadIdx.x;
    const float* src;
    __nv_bfloat16* dst;
    int j;
    if (i < nz4)            { src = z;   dst = zb; j = i; }
    else if (i < nz4 + ne4) { src = emb; dst = eb; j = i - nz4; }
    else return;
    float4 v = ((const float4*)src)[j];
    __nv_bfloat162 p0 = __floats2bfloat162_rn(v.x, v.y);
    __nv_bfloat162 p1 = __floats2bfloat162_rn(v.z, v.w);
    uint2 w;
    w.x = *reinterpret_cast<unsigned*>(&p0);
    w.y = *reinterpret_cast<unsigned*>(&p1);
    ((uint2*)dst)[j] = w;
}

__global__ void rowsq_kernel(const float* __restrict__ emb,
                             const float* __restrict__ z,
                             int K, int B)
{
    int w    = (blockIdx.x * blockDim.x + threadIdx.x) >> 5;
    int lane = threadIdx.x & 31;
    if (w >= K + B) return;
    const float* src = (w < K) ? (emb + (size_t)w * DDIM)
                               : (z   + (size_t)(w - K) * DDIM);
    float s = 0.f;
#pragma unroll
    for (int t = 0; t < DDIM / 32; t++) {
        float x = src[lane + 32 * t];
        s = fmaf(x, x, s);
    }
#pragma unroll
    for (int off = 16; off > 0; off >>= 1)
        s += __shfl_xor_sync(0xFFFFFFFFu, s, off);
    if (lane == 0) {
        if (w < K) g_ee[w] = s;
        else       g_zz[w - K] = s;
    }
}

// ---- Phase 1: champion GEMM + in-smem candidate collection ---------------
__global__ __launch_bounds__(128, 2)
void vq_phase1_kernel(int K)
{
    extern __shared__ __half smem[];
    __shared__ float    sEE[BN];
    __shared__ float    sW[256];           // per-warp per-row tile mins
    __shared__ float    sRun[BM];          // running row min
    __shared__ int      sCnt[BM];
    __shared__ unsigned sCand[BM * CAP];   // packed (s_fp16 << 16) | k_u16

    const int tid   = threadIdx.x;
    const int wid   = tid >> 5;
    const int lane  = tid & 31;
    const int g     = lane >> 2;
    const int t     = lane & 3;
    const int warpN = wid;
    const int brow  = blockIdx.x * BM;

    if (tid < BM) { sRun[tid] = 3.4e38f; sCnt[tid] = 0; }

    int acr[2], acc_[2];
#pragma unroll
    for (int i = 0; i < 2; i++) {
        int idx = tid + i * 128;
        acr[i]  = idx >> 2;
        acc_[i] = (idx & 3) * 8;
    }
    int bcr[8], bcc[8];
#pragma unroll
    for (int i = 0; i < 8; i++) {
        int idx = tid + i * 128;
        bcr[i] = idx >> 2;
        bcc[i] = (idx & 3) * 8;
    }

    const int aRow = lane & 15;
    const int aCol = (lane >> 4) << 3;
    const int bRow = (lane & 7) + ((lane & 16) >> 1);
    const int bCol = lane & 8;

    const int NCH = (K / BN) * 16;

    {
        __half* bA = smem;
        __half* bB = smem + ABUF_H;
#pragma unroll
        for (int i = 0; i < 2; i++)
            cp16(bA + acr[i] * SA + acc_[i],
                 g_zb + (size_t)(brow + acr[i]) * DDIM + acc_[i]);
#pragma unroll
        for (int i = 0; i < 8; i++)
            cp16(bB + bcr[i] * SA + bcc[i],
                 g_eb + (size_t)bcr[i] * DDIM + bcc[i]);
        cp_commit();
    }

    float acc[4][8][4];
#pragma unroll
    for (int mt = 0; mt < 4; mt++)
#pragma unroll
        for (int nt = 0; nt < 8; nt++)
#pragma unroll
            for (int r = 0; r < 4; r++) acc[mt][nt][r] = 0.f;

    for (int c = 0; c < NCH; c++) {
        const int dch = c & 15;
        const int kt  = (c >> 4) * BN;
        __half* bA = smem + (c & 1) * BUF_H;
        __half* bB = bA + ABUF_H;

        cp_wait0();
        __syncthreads();

        if (dch == 0) {
            sEE[tid]       = g_ee[kt + tid];
            sEE[tid + 128] = g_ee[kt + tid + 128];
        }

        if (c + 1 < NCH) {
            const int ndb = ((c + 1) & 15) * 32;
            const int nkt = ((c + 1) >> 4) * BN;
            __half* nA = smem + ((c + 1) & 1) * BUF_H;
            __half* nB = nA + ABUF_H;
#pragma unroll
            for (int i = 0; i < 2; i++)
                cp16(nA + acr[i] * SA + acc_[i],
                     g_zb + (size_t)(brow + acr[i]) * DDIM + ndb + acc_[i]);
#pragma unroll
            for (int i = 0; i < 8; i++)
                cp16(nB + bcr[i] * SA + bcc[i],
                     g_eb + (size_t)(nkt + bcr[i]) * DDIM + ndb + bcc[i]);
            cp_commit();
        }

#pragma unroll
        for (int ks = 0; ks < 2; ks++) {
            const int kb = ks * 16;
            unsigned A[4][4], Bf[4][4];
#pragma unroll
            for (int mt = 0; mt < 4; mt++)
                ldsm4(A[mt], smem_u32(&bA[(mt * 16 + aRow) * SA + kb + aCol]));
#pragma unroll
            for (int np = 0; np < 4; np++)
                ldsm4(Bf[np], smem_u32(&bB[(warpN * 64 + np * 16 + bRow) * SA + kb + bCol]));
#pragma unroll
            for (int mt = 0; mt < 4; mt++)
#pragma unroll
                for (int nt = 0; nt < 8; nt++)
                    mma_bf16(acc[mt][nt], A[mt],
                             Bf[nt >> 1][(nt & 1) * 2], Bf[nt >> 1][(nt & 1) * 2 + 1]);
        }

        if (dch == 15) {
            // ---- pass 1: per-warp per-row tile mins -> merge to sRun
#pragma unroll
            for (int mt = 0; mt < 4; mt++)
#pragma unroll
                for (int i = 0; i < 2; i++) {
                    float v = 3.4e38f;
#pragma unroll
                    for (int nt = 0; nt < 8; nt++) {
                        int col = warpN * 64 + nt * 8 + 2 * t;
                        float s0 = fmaf(-2.f, acc[mt][nt][i * 2 + 0], sEE[col]);
                        float s1 = fmaf(-2.f, acc[mt][nt][i * 2 + 1], sEE[col + 1]);
                        float m = (s0 < s1) ? s0 : s1;
                        if (m < v) v = m;
                    }
#pragma unroll
                    for (int off = 1; off < 4; off <<= 1) {
                        float ov = __shfl_xor_sync(0xFFFFFFFFu, v, off);
                        if (ov < v) v = ov;
                    }
                    if (t == 0)
                        sW[warpN * 64 + mt * 16 + i * 8 + g] = v;
                }
            __syncthreads();
            if (tid < BM) {
                float v0 = sW[tid];
                float v1 = sW[64 + tid];
                float v2 = sW[128 + tid];
                float v3 = sW[192 + tid];
                float m01 = (v1 < v0) ? v1 : v0;
                float m23 = (v3 < v2) ? v3 : v2;
                float m   = (m23 < m01) ? m23 : m01;
                if (m < sRun[tid]) sRun[tid] = m;
            }
            __syncthreads();
            // ---- pass 2: candidate append vs running threshold
#pragma unroll
            for (int mt = 0; mt < 4; mt++)
#pragma unroll
                for (int i = 0; i < 2; i++) {
                    const int row = mt * 16 + i * 8 + g;
                    const float th = sRun[row] + MARGIN;
#pragma unroll
                    for (int nt = 0; nt < 8; nt++) {
                        int col = warpN * 64 + nt * 8 + 2 * t;
                        float s0 = fmaf(-2.f, acc[mt][nt][i * 2 + 0], sEE[col]);
                        float s1 = fmaf(-2.f, acc[mt][nt][i * 2 + 1], sEE[col + 1]);
                        if (s0 <= th) {
                            int pos = atomicAdd(&sCnt[row], 1);
                            if (pos < CAP)
                                sCand[row * CAP + pos] =
                                    ((unsigned)__half_as_ushort(__float2half_rn(s0)) << 16)
                                    | (unsigned)(kt + col);
                        }
                        if (s1 <= th) {
                            int pos = atomicAdd(&sCnt[row], 1);
                            if (pos < CAP)
                                sCand[row * CAP + pos] =
                                    ((unsigned)__half_as_ushort(__float2half_rn(s1)) << 16)
                                    | (unsigned)(kt + col + 1);
                        }
                        acc[mt][nt][i * 2 + 0] = 0.f;
                        acc[mt][nt][i * 2 + 1] = 0.f;
                    }
                }
        }
    }

    // ---- final outputs
    __syncthreads();
    if (tid < BM) {
        g_rmin[brow + tid] = sRun[tid];
        g_ccnt[brow + tid] = sCnt[tid];
    }
#pragma unroll
    for (int i = 0; i < (BM * CAP) / 128; i++) {
        int idx = tid + i * 128;
        g_cand[(size_t)(brow + (idx >> 6)) * CAP + (idx & 63)] = sCand[idx];
    }
}

// ---- Phase 2: tiny rescue (64 thr/row) + gather + loss -------------------
__global__ __launch_bounds__(64)
void rescue_kernel(const float* __restrict__ z,
                   const float* __restrict__ emb,
                   float* __restrict__ out_zq,
                   float* __restrict__ out_idx, int K)
{
    __shared__ float  sv[64];
    __shared__ int    si[64];
    __shared__ double sred[64];

    const int row = blockIdx.x;
    const int tid = threadIdx.x;

    const int   cnt    = g_ccnt[row];
    const float thresh = g_rmin[row] + MARGIN;
    const float zz     = g_zz[row];
    const float4* zp   = (const float4*)(z + (size_t)row * DDIM);

    float v  = 3.4e38f;
    int   bi = 0x7FFFFFFF;

    if (cnt <= CAP) {
        if (tid < cnt) {
            unsigned e = g_cand[(size_t)row * CAP + tid];
            float s = __half2float(__ushort_as_half((unsigned short)(e >> 16)));
            int   k = (int)(e & 0xFFFFu);
            if (s <= thresh) {
                const float4* ep = (const float4*)(emb + (size_t)k * DDIM);
                float accd = 0.f;
#pragma unroll 4
                for (int d = 0; d < DDIM / 4; d++) {
                    float4 za = zp[d], ea = ep[d];
                    accd = fmaf(za.x, ea.x, accd);
                    accd = fmaf(za.y, ea.y, accd);
                    accd = fmaf(za.z, ea.z, accd);
                    accd = fmaf(za.w, ea.w, accd);
                }
                float q = fmaf(-2.f, accd, zz) + g_ee[k];
                if (q < v || (q == v && k < bi)) { v = q; bi = k; }
            }
        }
    } else {
        // overflow fallback: exact scan of the whole row
        for (int k = tid; k < K; k += 64) {
            const float4* ep = (const float4*)(emb + (size_t)k * DDIM);
            float accd = 0.f;
#pragma unroll 4
            for (int d = 0; d < DDIM / 4; d++) {
                float4 za = zp[d], ea = ep[d];
                accd = fmaf(za.x, ea.x, accd);
                accd = fmaf(za.y, ea.y, accd);
                accd = fmaf(za.z, ea.z, accd);
                accd = fmaf(za.w, ea.w, accd);
            }
            float q = fmaf(-2.f, accd, zz) + g_ee[k];
            if (q < v || (q == v && k < bi)) { v = q; bi = k; }
        }
    }

    sv[tid] = v;
    si[tid] = bi;
    __syncthreads();
#pragma unroll
    for (int s = 32; s > 0; s >>= 1) {
        if (tid < s) {
            float ov = sv[tid + s];
            int   oi = si[tid + s];
            if (ov < sv[tid] || (ov == sv[tid] && oi < si[tid])) {
                sv[tid] = ov; si[tid] = oi;
            }
        }
        __syncthreads();
    }

    // fused gather + z_q_st + loss partial
    const int idx = si[0];
    if (tid == 0 && out_idx) out_idx[row] = (float)idx;

    const float4* ep = (const float4*)(emb + (size_t)idx * DDIM);
    double lsum = 0.0;
#pragma unroll
    for (int j = 0; j < 2; j++) {
        int d = tid + j * 64;
        float4 zv = zp[d];
        float4 ev = ep[d];
        float4 o;
        float dx;
        dx = ev.x - zv.x; o.x = zv.x + dx; lsum += (double)dx * (double)dx;
        dx = ev.y - zv.y; o.y = zv.y + dx; lsum += (double)dx * (double)dx;
        dx = ev.z - zv.z; o.z = zv.z + dx; lsum += (double)dx * (double)dx;
        dx = ev.w - zv.w; o.w = zv.w + dx; lsum += (double)dx * (double)dx;
        ((float4*)(out_zq + (size_t)row * DDIM))[d] = o;
    }

    sred[tid] = lsum;
    __syncthreads();
#pragma unroll
    for (int s = 32; s > 0; s >>= 1) {
        if (tid < s) sred[tid] += sred[tid + s];
        __syncthreads();
    }
    if (tid == 0) g_part[row] = sred[0];
}

__global__ void finalize_kernel(float* __restrict__ out_loss, int nparts, double scale)
{
    __shared__ double sred[512];
    int tid = threadIdx.x;
    double s = 0.0;
    for (int i = tid; i < nparts; i += 512) s += g_part[i];   // fixed order
    sred[tid] = s;
    __syncthreads();
#pragma unroll
    for (int st = 256; st > 0; st >>= 1) {
        if (tid < st) sred[tid] += sred[tid + st];
        __syncthreads();
    }
    if (tid == 0) *out_loss = (float)(sred[0] * scale);
}

// -------------------------------------------------------------------------
extern "C" void kernel_launch(void* const* d_in, const int* in_sizes, int n_in,
                              void* d_out, int out_size)
{
    const float* z   = (const float*)d_in[0];
    const float* emb = (const float*)d_in[1];
    int B = in_sizes[0] / DDIM;   // 16384
    int K = in_sizes[1] / DDIM;   // 8192

    float* out      = (float*)d_out;
    float* out_zq   = out;
    float* out_idx  = ((size_t)out_size >= (size_t)B * DDIM + (size_t)B)
                        ? out + (size_t)B * DDIM : nullptr;
    float* out_loss = ((size_t)out_size >= (size_t)B * DDIM + (size_t)B + 1)
                        ? out + (size_t)B * DDIM + B : nullptr;

    __nv_bfloat16 *zb, *eb;
    cudaGetSymbolAddress((void**)&zb, g_zb);
    cudaGetSymbolAddress((void**)&eb, g_eb);

    static int smem_set = 0;
    const int dyn_smem = 2 * BUF_H * 2;   // 51200 B
    if (!smem_set) {
        cudaFuncSetAttribute(vq_phase1_kernel,
                             cudaFuncAttributeMaxDynamicSharedMemorySize, dyn_smem);
        smem_set = 1;
    }

    int nz4 = B * DDIM / 4, ne4 = K * DDIM / 4;
    to_bf16_both_kernel<<<(nz4 + ne4 + 255) / 256, 256>>>(z, emb, zb, eb, nz4, ne4);
    rowsq_kernel<<<((K + B) * 32 + 255) / 256, 256>>>(emb, z, K, B);

    vq_phase1_kernel<<<B / BM, 128, dyn_smem>>>(K);
    rescue_kernel<<<B, 64>>>(z, emb, out_zq, out_idx, K);

    if (out_loss)
        finalize_kernel<<<1, 512>>>(out_loss, B, 1.25 / ((double)B * (double)DDIM));
}

// round 16
// speedup vs baseline: 2.2443x; 2.2443x over previous
#include <cuda_runtime.h>
#include <cuda_bf16.h>
#include <cuda_fp16.h>
#include <cstdint>
#include <cstddef>

// VectorQuantizer, two-phase:
//   Phase 1: bf16 ldmatrix+mma GEMM (champion R11 hot loop + epilogue shape,
//            BM=64 x BN=256, 4 warps, 64x64 warp tiles, 2 CTAs/SM) ->
//            int8 screen q[b,k] = rn(2000*(ee - 2*G)) (128 MB) + per-row fp32 min.
//   Phase 2: fused per-row scan of int8 screen (integer compares vs final-min
//            threshold) -> compact candidates -> exact fp32 rescue
//            (bit-identical Round-2 chain) -> z_q_st gather + loss partial.
// Output: [ z_q_st (B*512) | indices as float (B) | vq_loss (1) ]

#define DDIM 512
#define NB 16384
#define NK 8192
#define BM 64
#define BN 256

#define SA 40                      // smem row stride in halves (80B, LDSM conflict-free)
#define ABUF_H (64 * SA)
#define BBUF_H (256 * SA)
#define BUF_H  (ABUF_H + BBUF_H)   // 12800 halves per pipeline buffer
#define STAGE_OFF_B (2 * BUF_H * 2)  // byte offset of int8 staging (51200)
#define STROW_B 272                // stage row stride in bytes (256 + 16 pad)

#define CAP 64
#define MARGIN 2e-3f
#define QSCALE 2000.0f

__device__ float  g_ee[NK];
__device__ float  g_zz[NB];
__device__ float  g_rmin[NB];
__device__ double g_part[NB];

__device__ __nv_bfloat16 g_zb[NB * DDIM];
__device__ __nv_bfloat16 g_eb[NK * DDIM];
__device__ signed char   g_s[(size_t)NB * NK];  // int8 screen, 128 MB

// ---- helpers -------------------------------------------------------------
__device__ __forceinline__ unsigned smem_u32(const void* p)
{
    return (unsigned)__cvta_generic_to_shared(p);
}
__device__ __forceinline__ void cp16(__half* sdst, const void* gsrc)
{
    asm volatile("cp.async.ca.shared.global [%0], [%1], 16;\n"
                 :: "r"(smem_u32(sdst)), "l"(gsrc));
}
__device__ __forceinline__ void cp_commit() { asm volatile("cp.async.commit_group;\n"); }
__device__ __forceinline__ void cp_wait0()  { asm volatile("cp.async.wait_group 0;\n"); }

__device__ __forceinline__ void ldsm4(unsigned* r, unsigned addr)
{
    asm volatile("ldmatrix.sync.aligned.m8n8.x4.shared.b16 {%0,%1,%2,%3}, [%4];"
                 : "=r"(r[0]), "=r"(r[1]), "=r"(r[2]), "=r"(r[3]) : "r"(addr));
}
__device__ __forceinline__ void mma_bf16(float* c, const unsigned* a,
                                         unsigned b0, unsigned b1)
{
    asm volatile(
        "mma.sync.aligned.m16n8k16.row.col.f32.bf16.bf16.f32 "
        "{%0,%1,%2,%3}, {%4,%5,%6,%7}, {%8,%9}, {%0,%1,%2,%3};\n"
        : "+f"(c[0]), "+f"(c[1]), "+f"(c[2]), "+f"(c[3])
        : "r"(a[0]), "r"(a[1]), "r"(a[2]), "r"(a[3]), "r"(b0), "r"(b1));
}
__device__ __forceinline__ signed char q8(float s)
{
    int q = __float2int_rn(s * QSCALE);
    q = (q > 127) ? 127 : q;
    q = (q < -127) ? -127 : q;
    return (signed char)q;
}

// ---- prep ----------------------------------------------------------------
__global__ void to_bf16_both_kernel(const float* __restrict__ z,
                                    const float* __restrict__ emb,
                                    __nv_bfloat16* __restrict__ zb,
                                    __nv_bfloat16* __restrict__ eb,
                                    int nz4, int ne4)
{
    int i = blockIdx.x * blockDim.x + threadIdx.x;
    const float* src;
    __nv_bfloat16* dst;
    int j;
    if (i < nz4)            { src = z;   dst = zb; j = i; }
    else if (i < nz4 + ne4) { src = emb; dst = eb; j = i - nz4; }
    else return;
    float4 v = ((const float4*)src)[j];
    __nv_bfloat162 p0 = __floats2bfloat162_rn(v.x, v.y);
    __nv_bfloat162 p1 = __floats2bfloat162_rn(v.z, v.w);
    uint2 w;
    w.x = *reinterpret_cast<unsigned*>(&p0);
    w.y = *reinterpret_cast<unsigned*>(&p1);
    ((uint2*)dst)[j] = w;
}

__global__ void rowsq_kernel(const float* __restrict__ emb,
                             const float* __restrict__ z,
                             int K, int B)
{
    int w    = (blockIdx.x * blockDim.x + threadIdx.x) >> 5;
    int lane = threadIdx.x & 31;
    if (w >= K + B) return;
    const float* src = (w < K) ? (emb + (size_t)w * DDIM)
                               : (z   + (size_t)(w - K) * DDIM);
    float s = 0.f;
#pragma unroll
    for (int t = 0; t < DDIM / 32; t++) {
        float x = src[lane + 32 * t];
        s = fmaf(x, x, s);
    }
#pragma unroll
    for (int off = 16; off > 0; off >>= 1)
        s += __shfl_xor_sync(0xFFFFFFFFu, s, off);
    if (lane == 0) {
        if (w < K) g_ee[w] = s;
        else       g_zz[w - K] = s;
    }
}

// ---- Phase 1: champion GEMM, int8 screen --------------------------------
__global__ __launch_bounds__(128, 2)
void vq_phase1_kernel(int K)
{
    extern __shared__ __half smem[];
    __shared__ float sEE[BN];

    const int tid   = threadIdx.x;
    const int wid   = tid >> 5;
    const int lane  = tid & 31;
    const int g     = lane >> 2;
    const int t     = lane & 3;
    const int warpN = wid;
    const int brow  = blockIdx.x * BM;

    float bestv[8];
#pragma unroll
    for (int a = 0; a < 8; a++) bestv[a] = 3.4e38f;

    int acr[2], acc_[2];
#pragma unroll
    for (int i = 0; i < 2; i++) {
        int idx = tid + i * 128;
        acr[i]  = idx >> 2;
        acc_[i] = (idx & 3) * 8;
    }
    int bcr[8], bcc[8];
#pragma unroll
    for (int i = 0; i < 8; i++) {
        int idx = tid + i * 128;
        bcr[i] = idx >> 2;
        bcc[i] = (idx & 3) * 8;
    }

    const int aRow = lane & 15;
    const int aCol = (lane >> 4) << 3;
    const int bRow = (lane & 7) + ((lane & 16) >> 1);
    const int bCol = lane & 8;

    const int NCH = (K / BN) * 16;

    {
        __half* bA = smem;
        __half* bB = smem + ABUF_H;
#pragma unroll
        for (int i = 0; i < 2; i++)
            cp16(bA + acr[i] * SA + acc_[i],
                 g_zb + (size_t)(brow + acr[i]) * DDIM + acc_[i]);
#pragma unroll
        for (int i = 0; i < 8; i++)
            cp16(bB + bcr[i] * SA + bcc[i],
                 g_eb + (size_t)bcr[i] * DDIM + bcc[i]);
        cp_commit();
    }

    float acc[4][8][4];
#pragma unroll
    for (int mt = 0; mt < 4; mt++)
#pragma unroll
        for (int nt = 0; nt < 8; nt++)
#pragma unroll
            for (int r = 0; r < 4; r++) acc[mt][nt][r] = 0.f;

    for (int c = 0; c < NCH; c++) {
        const int dch = c & 15;
        const int kt  = (c >> 4) * BN;
        __half* bA = smem + (c & 1) * BUF_H;
        __half* bB = bA + ABUF_H;

        cp_wait0();
        __syncthreads();

        if (dch == 0) {
            sEE[tid]       = g_ee[kt + tid];
            sEE[tid + 128] = g_ee[kt + tid + 128];
        }

        if (c + 1 < NCH) {
            const int ndb = ((c + 1) & 15) * 32;
            const int nkt = ((c + 1) >> 4) * BN;
            __half* nA = smem + ((c + 1) & 1) * BUF_H;
            __half* nB = nA + ABUF_H;
#pragma unroll
            for (int i = 0; i < 2; i++)
                cp16(nA + acr[i] * SA + acc_[i],
                     g_zb + (size_t)(brow + acr[i]) * DDIM + ndb + acc_[i]);
#pragma unroll
            for (int i = 0; i < 8; i++)
                cp16(nB + bcr[i] * SA + bcc[i],
                     g_eb + (size_t)(nkt + bcr[i]) * DDIM + ndb + bcc[i]);
            cp_commit();
        }

#pragma unroll
        for (int ks = 0; ks < 2; ks++) {
            const int kb = ks * 16;
            unsigned A[4][4], Bf[4][4];
#pragma unroll
            for (int mt = 0; mt < 4; mt++)
                ldsm4(A[mt], smem_u32(&bA[(mt * 16 + aRow) * SA + kb + aCol]));
#pragma unroll
            for (int np = 0; np < 4; np++)
                ldsm4(Bf[np], smem_u32(&bB[(warpN * 64 + np * 16 + bRow) * SA + kb + bCol]));
#pragma unroll
            for (int mt = 0; mt < 4; mt++)
#pragma unroll
                for (int nt = 0; nt < 8; nt++)
                    mma_bf16(acc[mt][nt], A[mt],
                             Bf[nt >> 1][(nt & 1) * 2], Bf[nt >> 1][(nt & 1) * 2 + 1]);
        }

        if (dch == 15) {
            signed char* stage = (signed char*)smem + STAGE_OFF_B;
#pragma unroll
            for (int mt = 0; mt < 4; mt++)
#pragma unroll
                for (int i = 0; i < 2; i++) {
                    const int a = mt * 2 + i;
                    const int srow = mt * 16 + i * 8 + g;
                    float v = 3.4e38f;
#pragma unroll
                    for (int nt = 0; nt < 8; nt++) {
                        int col = warpN * 64 + nt * 8 + 2 * t;
                        float s0 = fmaf(-2.f, acc[mt][nt][i * 2 + 0], sEE[col]);
                        float s1 = fmaf(-2.f, acc[mt][nt][i * 2 + 1], sEE[col + 1]);
                        char2 pk;
                        pk.x = q8(s0);
                        pk.y = q8(s1);
                        *(char2*)&stage[srow * STROW_B + col] = pk;
                        float m = (s0 < s1) ? s0 : s1;
                        if (m < v) v = m;
                    }
#pragma unroll
                    for (int off = 1; off < 4; off <<= 1) {
                        float ov = __shfl_xor_sync(0xFFFFFFFFu, v, off);
                        if (ov < v) v = ov;
                    }
                    if (v < bestv[a]) bestv[a] = v;
                }
#pragma unroll
            for (int mt = 0; mt < 4; mt++)
#pragma unroll
                for (int nt = 0; nt < 8; nt++)
#pragma unroll
                    for (int r = 0; r < 4; r++) acc[mt][nt][r] = 0.f;

            __syncthreads();
            // cooperative store staging -> g_s (int8): 64 rows x 16 float4 = 1024
#pragma unroll
            for (int i = 0; i < 8; i++) {
                int idx = tid + i * 128;
                int row = idx >> 4;
                int c16 = idx & 15;
                float4 v4 = *(const float4*)&stage[row * STROW_B + c16 * 16];
                *(float4*)&g_s[(size_t)(brow + row) * K + kt + c16 * 16] = v4;
            }
        }
    }

    // merge the four warpN quarters -> per-row min
    __syncthreads();
    float* sv = (float*)((signed char*)smem + STAGE_OFF_B);   // reuse staging
    if (t == 0) {
#pragma unroll
        for (int a = 0; a < 8; a++) {
            int row = (a >> 1) * 16 + (a & 1) * 8 + g;
            sv[warpN * 64 + row] = bestv[a];
        }
    }
    __syncthreads();
    if (tid < BM) {
        float v0 = sv[tid];
        float v1 = sv[64 + tid];
        float v2 = sv[128 + tid];
        float v3 = sv[192 + tid];
        float m01 = (v1 < v0) ? v1 : v0;
        float m23 = (v3 < v2) ? v3 : v2;
        g_rmin[brow + tid] = (m23 < m01) ? m23 : m01;
    }
}

// ---- Phase 2: fused int8 scan + compact + exact rescue + gather + loss ---
__global__ __launch_bounds__(128)
void scan_rescue_kernel(const float* __restrict__ z,
                        const float* __restrict__ emb,
                        float* __restrict__ out_zq,
                        float* __restrict__ out_idx, int K)
{
    __shared__ int    sCand[CAP];
    __shared__ int    sCnt;
    __shared__ float  sv[128];
    __shared__ int    si[128];
    __shared__ double sred[128];

    const int row = blockIdx.x;
    const int tid = threadIdx.x;

    if (tid == 0) sCnt = 0;
    __syncthreads();

    // integer threshold: q <= qthresh covers s_true <= rmin + winner band
    int qthresh = __float2int_rn((g_rmin[row] + MARGIN) * QSCALE);
    if (qthresh > 127) qthresh = 127;

    const uint4* srow = (const uint4*)(g_s + (size_t)row * K);   // 512 uint4

    for (int j = 0; j < K / (128 * 16); j++) {     // 4 iterations
        int u4i = tid + j * 128;
        uint4 u = srow[u4i];
        unsigned uw[4] = {u.x, u.y, u.z, u.w};
#pragma unroll
        for (int wsel = 0; wsel < 4; wsel++) {
            unsigned w = uw[wsel];
#pragma unroll
            for (int b = 0; b < 4; b++) {
                int qv = (int)((signed char)(w >> (8 * b)));
                if (qv <= qthresh) {
                    int pos = atomicAdd(&sCnt, 1);
                    if (pos < CAP) sCand[pos] = u4i * 16 + wsel * 4 + b;
                }
            }
        }
    }
    __syncthreads();
    const int cnt = sCnt;

    const float zz   = g_zz[row];
    const float4* zp = (const float4*)(z + (size_t)row * DDIM);

    float v  = 3.4e38f;
    int   bi = 0x7FFFFFFF;

    if (cnt <= CAP) {
        for (int ci = tid; ci < cnt; ci += 128) {
            int k = sCand[ci];
            const float4* ep = (const float4*)(emb + (size_t)k * DDIM);
            float accd = 0.f;
#pragma unroll 4
            for (int d = 0; d < DDIM / 4; d++) {
                float4 za = zp[d], ea = ep[d];
                accd = fmaf(za.x, ea.x, accd);
                accd = fmaf(za.y, ea.y, accd);
                accd = fmaf(za.z, ea.z, accd);
                accd = fmaf(za.w, ea.w, accd);
            }
            float q = fmaf(-2.f, accd, zz) + g_ee[k];
            if (q < v || (q == v && k < bi)) { v = q; bi = k; }
        }
    } else {
        for (int k = tid; k < K; k += 128) {
            const float4* ep = (const float4*)(emb + (size_t)k * DDIM);
            float accd = 0.f;
#pragma unroll 4
            for (int d = 0; d < DDIM / 4; d++) {
                float4 za = zp[d], ea = ep[d];
                accd = fmaf(za.x, ea.x, accd);
                accd = fmaf(za.y, ea.y, accd);
                accd = fmaf(za.z, ea.z, accd);
                accd = fmaf(za.w, ea.w, accd);
            }
            float q = fmaf(-2.f, accd, zz) + g_ee[k];
            if (q < v || (q == v && k < bi)) { v = q; bi = k; }
        }
    }

    sv[tid] = v;
    si[tid] = bi;
    __syncthreads();
#pragma unroll
    for (int s = 64; s > 0; s >>= 1) {
        if (tid < s) {
            float ov = sv[tid + s];
            int   oi = si[tid + s];
            if (ov < sv[tid] || (ov == sv[tid] && oi < si[tid])) {
                sv[tid] = ov; si[tid] = oi;
            }
        }
        __syncthreads();
    }

    // fused gather + z_q_st + loss partial
    const int idx = si[0];
    if (tid == 0 && out_idx) out_idx[row] = (float)idx;

    float4 zv = zp[tid];
    float4 ev = ((const float4*)(emb + (size_t)idx * DDIM))[tid];
    float4 o;
    double lsum = 0.0;
    float dx;
    dx = ev.x - zv.x; o.x = zv.x + dx; lsum += (double)dx * (double)dx;
    dx = ev.y - zv.y; o.y = zv.y + dx; lsum += (double)dx * (double)dx;
    dx = ev.z - zv.z; o.z = zv.z + dx; lsum += (double)dx * (double)dx;
    dx = ev.w - zv.w; o.w = zv.w + dx; lsum += (double)dx * (double)dx;
    ((float4*)(out_zq + (size_t)row * DDIM))[tid] = o;

    sred[tid] = lsum;
    __syncthreads();
#pragma unroll
    for (int s = 64; s > 0; s >>= 1) {
        if (tid < s) sred[tid] += sred[tid + s];
        __syncthreads();
    }
    if (tid == 0) g_part[row] = sred[0];
}

__global__ void finalize_kernel(float* __restrict__ out_loss, int nparts, double scale)
{
    __shared__ double sred[512];
    int tid = threadIdx.x;
    double s = 0.0;
    for (int i = tid; i < nparts; i += 512) s += g_part[i];   // fixed order
    sred[tid] = s;
    __syncthreads();
#pragma unroll
    for (int st = 256; st > 0; st >>= 1) {
        if (tid < st) sred[tid] += sred[tid + st];
        __syncthreads();
    }
    if (tid == 0) *out_loss = (float)(sred[0] * scale);
}

// -------------------------------------------------------------------------
extern "C" void kernel_launch(void* const* d_in, const int* in_sizes, int n_in,
                              void* d_out, int out_size)
{
    const float* z   = (const float*)d_in[0];
    const float* emb = (const float*)d_in[1];
    int B = in_sizes[0] / DDIM;   // 16384
    int K = in_sizes[1] / DDIM;   // 8192

    float* out      = (float*)d_out;
    float* out_zq   = out;
    float* out_idx  = ((size_t)out_size >= (size_t)B * DDIM + (size_t)B)
                        ? out + (size_t)B * DDIM : nullptr;
    float* out_loss = ((size_t)out_size >= (size_t)B * DDIM + (size_t)B + 1)
                        ? out + (size_t)B * DDIM + B : nullptr;

    __nv_bfloat16 *zb, *eb;
    cudaGetSymbolAddress((void**)&zb, g_zb);
    cudaGetSymbolAddress((void**)&eb, g_eb);

    static int smem_set = 0;
    const int dyn_smem = STAGE_OFF_B + BM * STROW_B;   // 51200 + 17408 = 68608 B
    if (!smem_set) {
        cudaFuncSetAttribute(vq_phase1_kernel,
                             cudaFuncAttributeMaxDynamicSharedMemorySize, dyn_smem);
        smem_set = 1;
    }

    int nz4 = B * DDIM / 4, ne4 = K * DDIM / 4;
    to_bf16_both_kernel<<<(nz4 + ne4 + 255) / 256, 256>>>(z, emb, zb, eb, nz4, ne4);
    rowsq_kernel<<<((K + B) * 32 + 255) / 256, 256>>>(emb, z, K, B);

    vq_phase1_kernel<<<B / BM, 128, dyn_smem>>>(K);
    scan_rescue_kernel<<<B, 128>>>(z, emb, out_zq, out_idx, K);

    if (out_loss)
        finalize_kernel<<<1, 512>>>(out_loss, B, 1.25 / ((double)B * (double)DDIM));
}

// round 17
// speedup vs baseline: 5.0821x; 2.2645x over previous
#include <cuda_runtime.h>
#include <cuda_bf16.h>
#include <cuda_fp16.h>
#include <cstdint>
#include <cstddef>

// VectorQuantizer, two-phase (restored R11 champion):
//   Phase 1: bf16 ldmatrix+mma GEMM, BM=64 x BN=256 tiles, 4 warps with fat
//            64x64 warp tiles, 2 CTAs/SM -> fp16 screen s[b,k] = ee - 2*G
//            (256 MB) + per-row fp32 min.
//   Phase 2: per-row scan of the screen (final-min + MARGIN) -> compact
//            candidates -> exact fp32 rescue (bit-identical Round-2 chain);
//            then separate gather_loss kernel (32 rows/block).
// Output: [ z_q_st (B*512) | indices as float (B) | vq_loss (1) ]

#define DDIM 512
#define NB 16384
#define NK 8192
#define BM 64
#define BN 256

#define SA 40                      // smem row stride in halves (80B, LDSM conflict-free)
#define ABUF_H (64 * SA)           // A tile: 64 rows   (2560 halves)
#define BBUF_H (256 * SA)          // B tile: 256 rows  (10240 halves)
#define BUF_H  (ABUF_H + BBUF_H)   // 12800 halves per pipeline buffer
#define STAGE_OFF_H (2 * BUF_H)    // 25600
#define STROW_H 264                // stage row stride in halves (256 + 8 pad)

#define CAP 64
#define MARGIN 2e-3f

__device__ float  g_ee[NK];
__device__ float  g_zz[NB];
__device__ float  g_rmin[NB];
__device__ int    g_best[NB];
__device__ double g_part[512];

__device__ __nv_bfloat16 g_zb[NB * DDIM];
__device__ __nv_bfloat16 g_eb[NK * DDIM];
__device__ __half        g_s[(size_t)NB * NK];  // fp16 screen, 256 MB

// ---- helpers -------------------------------------------------------------
__device__ __forceinline__ unsigned smem_u32(const void* p)
{
    return (unsigned)__cvta_generic_to_shared(p);
}
__device__ __forceinline__ void cp16(__half* sdst, const void* gsrc)
{
    asm volatile("cp.async.ca.shared.global [%0], [%1], 16;\n"
                 :: "r"(smem_u32(sdst)), "l"(gsrc));
}
__device__ __forceinline__ void cp_commit() { asm volatile("cp.async.commit_group;\n"); }
__device__ __forceinline__ void cp_wait0()  { asm volatile("cp.async.wait_group 0;\n"); }

__device__ __forceinline__ void ldsm4(unsigned* r, unsigned addr)
{
    asm volatile("ldmatrix.sync.aligned.m8n8.x4.shared.b16 {%0,%1,%2,%3}, [%4];"
                 : "=r"(r[0]), "=r"(r[1]), "=r"(r[2]), "=r"(r[3]) : "r"(addr));
}
__device__ __forceinline__ void mma_bf16(float* c, const unsigned* a,
                                         unsigned b0, unsigned b1)
{
    asm volatile(
        "mma.sync.aligned.m16n8k16.row.col.f32.bf16.bf16.f32 "
        "{%0,%1,%2,%3}, {%4,%5,%6,%7}, {%8,%9}, {%0,%1,%2,%3};\n"
        : "+f"(c[0]), "+f"(c[1]), "+f"(c[2]), "+f"(c[3])
        : "r"(a[0]), "r"(a[1]), "r"(a[2]), "r"(a[3]), "r"(b0), "r"(b1));
}

// ---- prep ----------------------------------------------------------------
__global__ void to_bf16_both_kernel(const float* __restrict__ z,
                                    const float* __restrict__ emb,
                                    __nv_bfloat16* __restrict__ zb,
                                    __nv_bfloat16* __restrict__ eb,
                                    int nz4, int ne4)
{
    int i = blockIdx.x * blockDim.x + threadIdx.x;
    const float* src;
    __nv_bfloat16* dst;
    int j;
    if (i < nz4)            { src = z;   dst = zb; j = i; }
    else if (i < nz4 + ne4) { src = emb; dst = eb; j = i - nz4; }
    else return;
    float4 v = ((const float4*)src)[j];
    __nv_bfloat162 p0 = __floats2bfloat162_rn(v.x, v.y);
    __nv_bfloat162 p1 = __floats2bfloat162_rn(v.z, v.w);
    uint2 w;
    w.x = *reinterpret_cast<unsigned*>(&p0);
    w.y = *reinterpret_cast<unsigned*>(&p1);
    ((uint2*)dst)[j] = w;
}

__global__ void rowsq_kernel(const float* __restrict__ emb,
                             const float* __restrict__ z,
                             int K, int B)
{
    int w    = (blockIdx.x * blockDim.x + threadIdx.x) >> 5;
    int lane = threadIdx.x & 31;
    if (w >= K + B) return;
    const float* src = (w < K) ? (emb + (size_t)w * DDIM)
                               : (z   + (size_t)(w - K) * DDIM);
    float s = 0.f;
#pragma unroll
    for (int t = 0; t < DDIM / 32; t++) {
        float x = src[lane + 32 * t];
        s = fmaf(x, x, s);
    }
#pragma unroll
    for (int off = 16; off > 0; off >>= 1)
        s += __shfl_xor_sync(0xFFFFFFFFu, s, off);
    if (lane == 0) {
        if (w < K) g_ee[w] = s;
        else       g_zz[w - K] = s;
    }
}

// ---- Phase 1: 128 thr = 4 warps (all warpN), warp tile 64x64, 2 CTAs/SM --
// (byte-for-byte the R11 champion kernel)
__global__ __launch_bounds__(128, 2)
void vq_phase1_kernel(int K)
{
    extern __shared__ __half smem[];
    __shared__ float sEE[BN];

    const int tid   = threadIdx.x;
    const int wid   = tid >> 5;
    const int lane  = tid & 31;
    const int g     = lane >> 2;
    const int t     = lane & 3;
    const int warpN = wid;           // 0..3, warp covers cols [warpN*64, +64)
    const int brow  = blockIdx.x * BM;

    float bestv[8];
#pragma unroll
    for (int a = 0; a < 8; a++) bestv[a] = 3.4e38f;

    // cp.async mapping
    int acr[2], acc_[2];               // A: 64 rows x 4 x 16B = 256 units, 2/thread
#pragma unroll
    for (int i = 0; i < 2; i++) {
        int idx = tid + i * 128;
        acr[i]  = idx >> 2;
        acc_[i] = (idx & 3) * 8;
    }
    int bcr[8], bcc[8];                // B: 256 rows x 4 x 16B = 1024 units, 8/thread
#pragma unroll
    for (int i = 0; i < 8; i++) {
        int idx = tid + i * 128;
        bcr[i] = idx >> 2;
        bcc[i] = (idx & 3) * 8;
    }

    // ldmatrix lane offsets (validated R6..R11)
    const int aRow = lane & 15;
    const int aCol = (lane >> 4) << 3;
    const int bRow = (lane & 7) + ((lane & 16) >> 1);
    const int bCol = lane & 8;

    const int NCH = (K / BN) * 16;    // 512

    // prologue: chunk 0 -> buffer 0
    {
        __half* bA = smem;
        __half* bB = smem + ABUF_H;
#pragma unroll
        for (int i = 0; i < 2; i++)
            cp16(bA + acr[i] * SA + acc_[i],
                 g_zb + (size_t)(brow + acr[i]) * DDIM + acc_[i]);
#pragma unroll
        for (int i = 0; i < 8; i++)
            cp16(bB + bcr[i] * SA + bcc[i],
                 g_eb + (size_t)bcr[i] * DDIM + bcc[i]);
        cp_commit();
    }

    float acc[4][8][4];
#pragma unroll
    for (int mt = 0; mt < 4; mt++)
#pragma unroll
        for (int nt = 0; nt < 8; nt++)
#pragma unroll
            for (int r = 0; r < 4; r++) acc[mt][nt][r] = 0.f;

    for (int c = 0; c < NCH; c++) {
        const int dch = c & 15;
        const int kt  = (c >> 4) * BN;
        __half* bA = smem + (c & 1) * BUF_H;
        __half* bB = bA + ABUF_H;

        cp_wait0();
        __syncthreads();

        if (dch == 0) {
            sEE[tid]       = g_ee[kt + tid];
            sEE[tid + 128] = g_ee[kt + tid + 128];
        }

        if (c + 1 < NCH) {
            const int ndb = ((c + 1) & 15) * 32;
            const int nkt = ((c + 1) >> 4) * BN;
            __half* nA = smem + ((c + 1) & 1) * BUF_H;
            __half* nB = nA + ABUF_H;
#pragma unroll
            for (int i = 0; i < 2; i++)
                cp16(nA + acr[i] * SA + acc_[i],
                     g_zb + (size_t)(brow + acr[i]) * DDIM + ndb + acc_[i]);
#pragma unroll
            for (int i = 0; i < 8; i++)
                cp16(nB + bcr[i] * SA + bcc[i],
                     g_eb + (size_t)(nkt + bcr[i]) * DDIM + ndb + bcc[i]);
            cp_commit();
        }

        // compute: 2 k16 steps, ldmatrix feeds
#pragma unroll
        for (int ks = 0; ks < 2; ks++) {
            const int kb = ks * 16;
            unsigned A[4][4], Bf[4][4];
#pragma unroll
            for (int mt = 0; mt < 4; mt++)
                ldsm4(A[mt], smem_u32(&bA[(mt * 16 + aRow) * SA + kb + aCol]));
#pragma unroll
            for (int np = 0; np < 4; np++)
                ldsm4(Bf[np], smem_u32(&bB[(warpN * 64 + np * 16 + bRow) * SA + kb + bCol]));
#pragma unroll
            for (int mt = 0; mt < 4; mt++)
#pragma unroll
                for (int nt = 0; nt < 8; nt++)
                    mma_bf16(acc[mt][nt], A[mt],
                             Bf[nt >> 1][(nt & 1) * 2], Bf[nt >> 1][(nt & 1) * 2 + 1]);
        }

        if (dch == 15) {
            __half* stage = smem + STAGE_OFF_H;
#pragma unroll
            for (int mt = 0; mt < 4; mt++)
#pragma unroll
                for (int i = 0; i < 2; i++) {
                    const int a = mt * 2 + i;
                    const int srow = mt * 16 + i * 8 + g;
                    float v = 3.4e38f;
#pragma unroll
                    for (int nt = 0; nt < 8; nt++) {
                        int col = warpN * 64 + nt * 8 + 2 * t;
                        float s0 = fmaf(-2.f, acc[mt][nt][i * 2 + 0], sEE[col]);
                        float s1 = fmaf(-2.f, acc[mt][nt][i * 2 + 1], sEE[col + 1]);
                        *(__half2*)&stage[srow * STROW_H + col] =
                            __floats2half2_rn(s0, s1);
                        float m = (s0 < s1) ? s0 : s1;
                        if (m < v) v = m;
                    }
#pragma unroll
                    for (int off = 1; off < 4; off <<= 1) {
                        float ov = __shfl_xor_sync(0xFFFFFFFFu, v, off);
                        if (ov < v) v = ov;
                    }
                    if (v < bestv[a]) bestv[a] = v;
                }
#pragma unroll
            for (int mt = 0; mt < 4; mt++)
#pragma unroll
                for (int nt = 0; nt < 8; nt++)
#pragma unroll
                    for (int r = 0; r < 4; r++) acc[mt][nt][r] = 0.f;

            __syncthreads();
            // cooperative store staging -> g_s (fp16): 64 rows x 32 float4 = 2048
#pragma unroll
            for (int i = 0; i < 16; i++) {
                int idx = tid + i * 128;
                int row = idx >> 5;
                int c8  = idx & 31;
                float4 v4 = *(const float4*)&stage[row * STROW_H + c8 * 8];
                *(float4*)&g_s[(size_t)(brow + row) * K + kt + c8 * 8] = v4;
            }
        }
    }

    // merge the four warpN quarters -> per-row min
    __syncthreads();
    float* sv = (float*)(smem + STAGE_OFF_H);   // [4][64]
    if (t == 0) {
#pragma unroll
        for (int a = 0; a < 8; a++) {
            int row = (a >> 1) * 16 + (a & 1) * 8 + g;
            sv[warpN * 64 + row] = bestv[a];
        }
    }
    __syncthreads();
    if (tid < BM) {
        float v0 = sv[tid];
        float v1 = sv[64 + tid];
        float v2 = sv[128 + tid];
        float v3 = sv[192 + tid];
        float m01 = (v1 < v0) ? v1 : v0;
        float m23 = (v3 < v2) ? v3 : v2;
        g_rmin[brow + tid] = (m23 < m01) ? m23 : m01;
    }
}

// ---- Phase 2: per-row scan + compact + exact rescue ----------------------
__global__ __launch_bounds__(128)
void scan_rescue_kernel(const float* __restrict__ z,
                        const float* __restrict__ emb, int K)
{
    __shared__ int   sCand[CAP];
    __shared__ int   sCnt;
    __shared__ float sv[128];
    __shared__ int   si[128];

    const int row = blockIdx.x;
    const int tid = threadIdx.x;

    if (tid == 0) sCnt = 0;
    __syncthreads();

    const float thresh = g_rmin[row] + MARGIN;
    const uint4* srow = (const uint4*)(g_s + (size_t)row * K);

    for (int j = 0; j < K / (128 * 8); j++) {
        int u4i = tid + j * 128;
        uint4 u = srow[u4i];
        unsigned uw[4] = {u.x, u.y, u.z, u.w};
#pragma unroll
        for (int p = 0; p < 4; p++) {
            float2 f = __half22float2(*reinterpret_cast<const __half2*>(&uw[p]));
            if (f.x <= thresh) {
                int pos = atomicAdd(&sCnt, 1);
                if (pos < CAP) sCand[pos] = u4i * 8 + p * 2;
            }
            if (f.y <= thresh) {
                int pos = atomicAdd(&sCnt, 1);
                if (pos < CAP) sCand[pos] = u4i * 8 + p * 2 + 1;
            }
        }
    }
    __syncthreads();
    const int cnt = sCnt;

    const float zz   = g_zz[row];
    const float4* zp = (const float4*)(z + (size_t)row * DDIM);

    float v  = 3.4e38f;
    int   bi = 0x7FFFFFFF;

    if (cnt <= CAP) {
        for (int ci = tid; ci < cnt; ci += 128) {
            int k = sCand[ci];
            const float4* ep = (const float4*)(emb + (size_t)k * DDIM);
            float accd = 0.f;
#pragma unroll 4
            for (int d = 0; d < DDIM / 4; d++) {
                float4 za = zp[d], ea = ep[d];
                accd = fmaf(za.x, ea.x, accd);
                accd = fmaf(za.y, ea.y, accd);
                accd = fmaf(za.z, ea.z, accd);
                accd = fmaf(za.w, ea.w, accd);
            }
            float q = fmaf(-2.f, accd, zz) + g_ee[k];
            if (q < v || (q == v && k < bi)) { v = q; bi = k; }
        }
    } else {
        for (int k = tid; k < K; k += 128) {
            const float4* ep = (const float4*)(emb + (size_t)k * DDIM);
            float accd = 0.f;
#pragma unroll 4
            for (int d = 0; d < DDIM / 4; d++) {
                float4 za = zp[d], ea = ep[d];
                accd = fmaf(za.x, ea.x, accd);
                accd = fmaf(za.y, ea.y, accd);
                accd = fmaf(za.z, ea.z, accd);
                accd = fmaf(za.w, ea.w, accd);
            }
            float q = fmaf(-2.f, accd, zz) + g_ee[k];
            if (q < v || (q == v && k < bi)) { v = q; bi = k; }
        }
    }

    sv[tid] = v;
    si[tid] = bi;
    __syncthreads();
#pragma unroll
    for (int s = 64; s > 0; s >>= 1) {
        if (tid < s) {
            float ov = sv[tid + s];
            int   oi = si[tid + s];
            if (ov < sv[tid] || (ov == sv[tid] && oi < si[tid])) {
                sv[tid] = ov; si[tid] = oi;
            }
        }
        __syncthreads();
    }
    if (tid == 0) g_best[row] = si[0];
}

// ---- output + loss -------------------------------------------------------
__global__ void gather_loss_kernel(const float* __restrict__ z,
                                   const float* __restrict__ emb,
                                   float* __restrict__ out_zq,
                                   float* __restrict__ out_idx,
                                   int B)
{
    __shared__ double sred[128];
    const int tid = threadIdx.x;
    double lsum = 0.0;

    for (int r = 0; r < 32; r++) {
        int b   = blockIdx.x * 32 + r;
        int idx = g_best[b];
        if (tid == 0 && out_idx) out_idx[b] = (float)idx;

        float4 zv = ((const float4*)(z   + (size_t)b   * DDIM))[tid];
        float4 ev = ((const float4*)(emb + (size_t)idx * DDIM))[tid];
        float4 o;
        float dx;
        dx = ev.x - zv.x; o.x = zv.x + dx; lsum += (double)dx * (double)dx;
        dx = ev.y - zv.y; o.y = zv.y + dx; lsum += (double)dx * (double)dx;
        dx = ev.z - zv.z; o.z = zv.z + dx; lsum += (double)dx * (double)dx;
        dx = ev.w - zv.w; o.w = zv.w + dx; lsum += (double)dx * (double)dx;
        ((float4*)(out_zq + (size_t)b * DDIM))[tid] = o;
    }

    sred[tid] = lsum;
    __syncthreads();
#pragma unroll
    for (int s = 64; s > 0; s >>= 1) {
        if (tid < s) sred[tid] += sred[tid + s];
        __syncthreads();
    }
    if (tid == 0) g_part[blockIdx.x] = sred[0];
}

__global__ void finalize_kernel(float* __restrict__ out_loss, int nparts, double scale)
{
    __shared__ double sred[512];
    int tid = threadIdx.x;
    sred[tid] = (tid < nparts) ? g_part[tid] : 0.0;
    __syncthreads();
#pragma unroll
    for (int s = 256; s > 0; s >>= 1) {
        if (tid < s) sred[tid] += sred[tid + s];
        __syncthreads();
    }
    if (tid == 0) *out_loss = (float)(sred[0] * scale);
}

// -------------------------------------------------------------------------
extern "C" void kernel_launch(void* const* d_in, const int* in_sizes, int n_in,
                              void* d_out, int out_size)
{
    const float* z   = (const float*)d_in[0];
    const float* emb = (const float*)d_in[1];
    int B = in_sizes[0] / DDIM;   // 16384
    int K = in_sizes[1] / DDIM;   // 8192

    float* out      = (float*)d_out;
    float* out_zq   = out;
    float* out_idx  = ((size_t)out_size >= (size_t)B * DDIM + (size_t)B)
                        ? out + (size_t)B * DDIM : nullptr;
    float* out_loss = ((size_t)out_size >= (size_t)B * DDIM + (size_t)B + 1)
                        ? out + (size_t)B * DDIM + B : nullptr;

    __nv_bfloat16 *zb, *eb;
    cudaGetSymbolAddress((void**)&zb, g_zb);
    cudaGetSymbolAddress((void**)&eb, g_eb);

    static int smem_set = 0;
    const int dyn_smem = (2 * BUF_H + BM * STROW_H) * 2;   // 84992 B
    if (!smem_set) {
        cudaFuncSetAttribute(vq_phase1_kernel,
                             cudaFuncAttributeMaxDynamicSharedMemorySize, dyn_smem);
        smem_set = 1;
    }

    int nz4 = B * DDIM / 4, ne4 = K * DDIM / 4;
    to_bf16_both_kernel<<<(nz4 + ne4 + 255) / 256, 256>>>(z, emb, zb, eb, nz4, ne4);
    rowsq_kernel<<<((K + B) * 32 + 255) / 256, 256>>>(emb, z, K, B);

    vq_phase1_kernel<<<B / BM, 128, dyn_smem>>>(K);
    scan_rescue_kernel<<<B, 128>>>(z, emb, K);

    int gblocks = B / 32;
    gather_loss_kernel<<<gblocks, 128>>>(z, emb, out_zq, out_idx, B);
    if (out_loss)
        finalize_kernel<<<1, 512>>>(out_loss, gblocks, 1.25 / ((double)B * (double)DDIM));
}